// round 14
// baseline (speedup 1.0000x reference)
#include <cuda_runtime.h>
#include <stdint.h>

#define NLV 16
#define LOG2T 19
#define TSIZE (1u << LOG2T)
#define TMASK (TSIZE - 1u)
#define BASE_RES 16
#define BLK 256            // 16 level-lanes x 8 thread-groups x 2 points = 32 points/block
#define PTS_PER_BLK 32

// precomputed normalization: [0..2]=bb_min, [3..5]=1/(bb_max-bb_min)
__device__ float g_norm[6];

__global__ void prep_kernel(const float* __restrict__ bb)
{
    if (threadIdx.x == 0) {
        #pragma unroll
        for (int i = 0; i < 3; ++i) {
            g_norm[i]     = bb[i];
            g_norm[3 + i] = 1.0f / (bb[3 + i] - bb[i]);
        }
    }
}

struct Corner8 {
    uint32_t e00, e01, e10, e11;   // x0 corners
    uint32_t f00, f01, f10, f11;   // x1 corners
    bool odd;
    float fx, fy, fz;
};

__device__ __forceinline__ void make_corners(
    float xnx, float xny, float xnz, int l, Corner8& c)
{
    const float resf = (float)(BASE_RES << l);
    const float posx = xnx * resf;
    const float posy = xny * resf;
    const float posz = xnz * resf;
    const float flx = floorf(posx);
    const float fly = floorf(posy);
    const float flz = floorf(posz);
    c.fx = posx - flx; c.fy = posy - fly; c.fz = posz - flz;

    const uint32_t ux = (uint32_t)(int32_t)flx;
    const uint32_t uy = (uint32_t)(int32_t)fly;
    const uint32_t uz = (uint32_t)(int32_t)flz;

    const uint32_t hy0 = uy * 2654435761u;
    const uint32_t hy1 = (uy + 1u) * 2654435761u;
    const uint32_t hz0 = uz * 805459861u;
    const uint32_t hz1 = (uz + 1u) * 805459861u;

    c.e00 = (ux ^ hy0 ^ hz0) & TMASK;
    c.e01 = (ux ^ hy0 ^ hz1) & TMASK;
    c.e10 = (ux ^ hy1 ^ hz0) & TMASK;
    c.e11 = (ux ^ hy1 ^ hz1) & TMASK;
    const uint32_t ux1 = ux + 1u;
    c.f00 = (ux1 ^ hy0 ^ hz0) & TMASK;
    c.f01 = (ux1 ^ hy0 ^ hz1) & TMASK;
    c.f10 = (ux1 ^ hy1 ^ hz0) & TMASK;
    c.f11 = (ux1 ^ hy1 ^ hz1) & TMASK;
    c.odd = (ux & 1u) != 0u;
}

__device__ __forceinline__ void blend(
    const Corner8& c,
    const float4 q00, const float4 q01, const float4 q10, const float4 q11,
    const float2 d00, const float2 d01, const float2 d10, const float2 d11,
    float& f0, float& f1)
{
    const bool h00 = (c.e00 & 1u), h01 = (c.e01 & 1u), h10 = (c.e10 & 1u), h11 = (c.e11 & 1u);

    const float2 c000 = h00 ? make_float2(q00.z, q00.w) : make_float2(q00.x, q00.y);
    const float2 c001 = h01 ? make_float2(q01.z, q01.w) : make_float2(q01.x, q01.y);
    const float2 c010 = h10 ? make_float2(q10.z, q10.w) : make_float2(q10.x, q10.y);
    const float2 c011 = h11 ? make_float2(q11.z, q11.w) : make_float2(q11.x, q11.y);

    float2 c100 = h00 ? make_float2(q00.x, q00.y) : make_float2(q00.z, q00.w);
    float2 c101 = h01 ? make_float2(q01.x, q01.y) : make_float2(q01.z, q01.w);
    float2 c110 = h10 ? make_float2(q10.x, q10.y) : make_float2(q10.z, q10.w);
    float2 c111 = h11 ? make_float2(q11.x, q11.y) : make_float2(q11.z, q11.w);
    if (c.odd) { c100 = d00; c101 = d01; c110 = d10; c111 = d11; }

    const float wx1 = c.fx, wx0 = 1.f - c.fx;
    const float wy1 = c.fy, wy0 = 1.f - c.fy;
    const float wz1 = c.fz, wz0 = 1.f - c.fz;

    float a0 = 0.f, a1 = 0.f, w;
    w = wx0 * wy0 * wz0; a0 += w * c000.x; a1 += w * c000.y;
    w = wx0 * wy0 * wz1; a0 += w * c001.x; a1 += w * c001.y;
    w = wx0 * wy1 * wz0; a0 += w * c010.x; a1 += w * c010.y;
    w = wx0 * wy1 * wz1; a0 += w * c011.x; a1 += w * c011.y;
    w = wx1 * wy0 * wz0; a0 += w * c100.x; a1 += w * c100.y;
    w = wx1 * wy0 * wz1; a0 += w * c101.x; a1 += w * c101.y;
    w = wx1 * wy1 * wz0; a0 += w * c110.x; a1 += w * c110.y;
    w = wx1 * wy1 * wz1; a0 += w * c111.x; a1 += w * c111.y;
    f0 = a0; f1 = a1;
}

__global__ __launch_bounds__(BLK) void hash_enc_2pt_kernel(
    const float* __restrict__ x,
    const float* __restrict__ table,
    float* __restrict__ out,
    float* __restrict__ mask_out,
    int n)
{
    const int tid = threadIdx.x;
    const int l  = tid & (NLV - 1);          // level
    const int pg = tid >> 4;                 // point-pair group (0..15)
    const long ptA = (long)blockIdx.x * PTS_PER_BLK + pg * 2;
    const long ptB = ptA + 1;
    const bool actA = ptA < n;
    const bool actB = ptB < n;
    if (!actA) return;

    const float bx0 = g_norm[0], by0 = g_norm[1], bz0 = g_norm[2];
    const float ix  = g_norm[3], iy  = g_norm[4], iz  = g_norm[5];

    // point A
    const float xnxA = (__ldg(x + ptA * 3 + 0) - bx0) * ix;
    const float xnyA = (__ldg(x + ptA * 3 + 1) - by0) * iy;
    const float xnzA = (__ldg(x + ptA * 3 + 2) - bz0) * iz;
    // point B (guarded)
    float xnxB = 0.f, xnyB = 0.f, xnzB = 0.f;
    if (actB) {
        xnxB = (__ldg(x + ptB * 3 + 0) - bx0) * ix;
        xnyB = (__ldg(x + ptB * 3 + 1) - by0) * iy;
        xnzB = (__ldg(x + ptB * 3 + 2) - bz0) * iz;
    }

    if (l == 0) {
        const bool mA = (xnxA > 0.f) & (xnxA < 1.f) &
                        (xnyA > 0.f) & (xnyA < 1.f) &
                        (xnzA > 0.f) & (xnzA < 1.f);
        mask_out[ptA] = mA ? 1.0f : 0.0f;
        if (actB) {
            const bool mB = (xnxB > 0.f) & (xnxB < 1.f) &
                            (xnyB > 0.f) & (xnyB < 1.f) &
                            (xnzB > 0.f) & (xnzB < 1.f);
            mask_out[ptB] = mB ? 1.0f : 0.0f;
        }
    }

    const float2* __restrict__ tbl2 = (const float2*)table + (size_t)l * TSIZE;
    const float4* __restrict__ tbl4 = (const float4*)tbl2;

    Corner8 cA, cB;
    make_corners(xnxA, xnyA, xnzA, l, cA);
    make_corners(actB ? xnxB : xnxA, actB ? xnyB : xnyA, actB ? xnzB : xnzA, l, cB);

    // front-batch all 8 float4 pair-loads (MLP = 8)
    const float4 qA00 = __ldg(tbl4 + (cA.e00 >> 1));
    const float4 qA01 = __ldg(tbl4 + (cA.e01 >> 1));
    const float4 qA10 = __ldg(tbl4 + (cA.e10 >> 1));
    const float4 qA11 = __ldg(tbl4 + (cA.e11 >> 1));
    const float4 qB00 = __ldg(tbl4 + (cB.e00 >> 1));
    const float4 qB01 = __ldg(tbl4 + (cB.e01 >> 1));
    const float4 qB10 = __ldg(tbl4 + (cB.e10 >> 1));
    const float4 qB11 = __ldg(tbl4 + (cB.e11 >> 1));

    // predicated odd-x loads for both points
    float2 dA00, dA01, dA10, dA11;
    if (cA.odd) {
        dA00 = __ldg(tbl2 + cA.f00);
        dA01 = __ldg(tbl2 + cA.f01);
        dA10 = __ldg(tbl2 + cA.f10);
        dA11 = __ldg(tbl2 + cA.f11);
    }
    float2 dB00, dB01, dB10, dB11;
    if (cB.odd) {
        dB00 = __ldg(tbl2 + cB.f00);
        dB01 = __ldg(tbl2 + cB.f01);
        dB10 = __ldg(tbl2 + cB.f10);
        dB11 = __ldg(tbl2 + cB.f11);
    }

    float fA0, fA1, fB0, fB1;
    blend(cA, qA00, qA01, qA10, qA11, dA00, dA01, dA10, dA11, fA0, fA1);
    blend(cB, qB00, qB01, qB10, qB11, dB00, dB01, dB10, dB11, fB0, fB1);

    float2* __restrict__ out2 = (float2*)out;
    out2[ptA * NLV + l] = make_float2(fA0, fA1);
    if (actB) out2[ptB * NLV + l] = make_float2(fB0, fB1);
}

extern "C" void kernel_launch(void* const* d_in, const int* in_sizes, int n_in,
                              void* d_out, int out_size)
{
    const float* x     = (const float*)d_in[0];   // [N,3]
    const float* bb    = (const float*)d_in[1];   // [6]
    const float* table = (const float*)d_in[2];   // [16, 2^19, 2]

    const int n = in_sizes[0] / 3;
    float* out = (float*)d_out;
    float* mask_out = out + (size_t)n * 32;       // enc [N,32] then mask [N]

    prep_kernel<<<1, 32>>>(bb);

    const int grid = (n + PTS_PER_BLK - 1) / PTS_PER_BLK;
    hash_enc_2pt_kernel<<<grid, BLK>>>(x, table, out, mask_out, n);
}